// round 7
// baseline (speedup 1.0000x reference)
#include <cuda_runtime.h>
#include <cuda_bf16.h>

// SpatialAttention, factored: m1@m2 = Qt(K Jt)K -> rank-8 bilinear form.
// R6: MSPLIT=1 — attn owns the full m-range per row-tile and fuses the
//     gamma*acc + x epilogue, writing d_out directly. finish_kernel removed.

#define BATCH 2
#define NSP   4096
#define NC    32
#define MT    64
#define BLK_ROWS 64          // 4 warps x 16 rows

typedef unsigned long long ull;
typedef unsigned int u32;

// ---- scratch ----
__device__ float g_Q[BATCH * NSP * 8];
__device__ float g_K[BATCH * NSP * 8];
__device__ float g_J[BATCH * NSP * 8];
__device__ __nv_bfloat16 g_Vt[BATCH * NC * NSP];   // [b][c][n] bf16
__device__ float g_M[BATCH * 64];                  // 0.5 * (K Jt)

#define XIDX(b,w,d,h,c) (((((((b)*16+(w))*16+(d))*16)+(h))*32)+(c))

__device__ __forceinline__ u32 cvt_bf2(float hi, float lo) {
    u32 r; asm("cvt.rn.bf16x2.f32 %0, %1, %2;" : "=r"(r) : "f"(hi), "f"(lo)); return r;
}
__device__ __forceinline__ u32 tanh_bf2(u32 x) {
    u32 r; asm("tanh.approx.bf16x2 %0, %1;" : "=r"(r) : "r"(x)); return r;
}
__device__ __forceinline__ u32 fma_bf2(u32 a, u32 b, u32 c) {
    u32 r; asm("fma.rn.bf16x2 %0, %1, %2, %3;" : "=r"(r) : "r"(a), "r"(b), "r"(c)); return r;
}
__device__ __forceinline__ u32 tf32c(float x) {
    u32 r; asm("cvt.rna.tf32.f32 %0, %1;" : "=r"(r) : "f"(x)); return r;
}
__device__ __forceinline__ void mma_tf32(float* c, const u32* a, u32 b0, u32 b1) {
    asm("mma.sync.aligned.m16n8k8.row.col.f32.tf32.tf32.f32 "
        "{%0,%1,%2,%3}, {%4,%5,%6,%7}, {%8,%9}, {%0,%1,%2,%3};"
        : "+f"(c[0]), "+f"(c[1]), "+f"(c[2]), "+f"(c[3])
        : "r"(a[0]), "r"(a[1]), "r"(a[2]), "r"(a[3]), "r"(b0), "r"(b1));
}
__device__ __forceinline__ void mma16816(float* c, const u32* a, u32 b0, u32 b1) {
    asm("mma.sync.aligned.m16n8k16.row.col.f32.bf16.bf16.f32 "
        "{%0,%1,%2,%3}, {%4,%5,%6,%7}, {%8,%9}, {%0,%1,%2,%3};"
        : "+f"(c[0]), "+f"(c[1]), "+f"(c[2]), "+f"(c[3])
        : "r"(a[0]), "r"(a[1]), "r"(a[2]), "r"(a[3]), "r"(b0), "r"(b1));
}
__device__ __forceinline__ void cp16(void* smem_dst, const void* gsrc) {
    u32 d = (u32)__cvta_generic_to_shared(smem_dst);
    asm volatile("cp.async.ca.shared.global [%0], [%1], 16;" :: "r"(d), "l"(gsrc));
}

// ============================================================
// 1) Projections
// ============================================================
__global__ __launch_bounds__(128) void proj_kernel(
    const float* __restrict__ x,
    const float* __restrict__ qw, const float* __restrict__ qb,
    const float* __restrict__ qs, const float* __restrict__ qo,
    const float* __restrict__ kw, const float* __restrict__ kb,
    const float* __restrict__ ks, const float* __restrict__ ko,
    const float* __restrict__ jw, const float* __restrict__ jb,
    const float* __restrict__ js, const float* __restrict__ jo,
    const float* __restrict__ vw, const float* __restrict__ vb,
    const float* __restrict__ vs, const float* __restrict__ vo)
{
    int d = blockIdx.x, w = blockIdx.y, b = blockIdx.z;
    int tid = threadIdx.x;

    __shared__ float s_c[18][33];
    __shared__ float s_dm[16][33], s_dp[16][33];
    __shared__ float s_wm[16][33], s_wp[16][33];
    __shared__ float s_qw[3][32][8], s_kw[3][32][8], s_jw[3][32][8];
    __shared__ float s_vw[32][32];

    for (int i = tid; i < 768; i += 128) {
        (&s_qw[0][0][0])[i] = qw[i];
        (&s_kw[0][0][0])[i] = kw[i];
        (&s_jw[0][0][0])[i] = jw[i];
    }
    for (int i = tid; i < 1024; i += 128) (&s_vw[0][0])[i] = vw[i];

    for (int i = tid; i < 512; i += 128) {
        int h = i >> 5, c = i & 31;
        s_c [h + 1][c] = x[XIDX(b, w, d, h, c)];
        s_dm[h][c] = (d > 0)  ? x[XIDX(b, w, d - 1, h, c)] : 0.f;
        s_dp[h][c] = (d < 15) ? x[XIDX(b, w, d + 1, h, c)] : 0.f;
        s_wm[h][c] = (w > 0)  ? x[XIDX(b, w - 1, d, h, c)] : 0.f;
        s_wp[h][c] = (w < 15) ? x[XIDX(b, w + 1, d, h, c)] : 0.f;
    }
    if (tid < 32)              s_c[0][tid]       = 0.f;
    else if (tid < 64)         s_c[17][tid - 32] = 0.f;
    __syncthreads();

    int h = tid >> 3, oc = tid & 7;
    float q = 0.f, k = 0.f, j = 0.f;
    float v0 = 0.f, v1 = 0.f, v2 = 0.f, v3 = 0.f;
    #pragma unroll
    for (int ci = 0; ci < 32; ci++) {
        float xc  = s_c [h + 1][ci];
        float xdm = s_dm[h][ci], xdp = s_dp[h][ci];
        float xwm = s_wm[h][ci], xwp = s_wp[h][ci];
        float xhm = s_c [h][ci], xhp = s_c [h + 2][ci];
        q += xdm * s_qw[0][ci][oc] + xc * s_qw[1][ci][oc] + xdp * s_qw[2][ci][oc];
        k += xwm * s_kw[0][ci][oc] + xc * s_kw[1][ci][oc] + xwp * s_kw[2][ci][oc];
        j += xhm * s_jw[0][ci][oc] + xc * s_jw[1][ci][oc] + xhp * s_jw[2][ci][oc];
        v0 += xc * s_vw[ci][oc];
        v1 += xc * s_vw[ci][oc + 8];
        v2 += xc * s_vw[ci][oc + 16];
        v3 += xc * s_vw[ci][oc + 24];
    }

    int n = w * 256 + d * 16 + h;
    g_Q[b * (NSP * 8) + n * 8 + oc] = fmaxf((q + qb[oc]) * qs[oc] + qo[oc], 0.f);
    g_K[b * (NSP * 8) + n * 8 + oc] = fmaxf((k + kb[oc]) * ks[oc] + ko[oc], 0.f);
    g_J[b * (NSP * 8) + n * 8 + oc] = fmaxf((j + jb[oc]) * js[oc] + jo[oc], 0.f);
    float vv[4] = {v0, v1, v2, v3};
    #pragma unroll
    for (int p = 0; p < 4; p++) {
        int co = oc + 8 * p;
        float val = fmaxf((vv[p] + vb[co]) * vs[co] + vo[co], 0.f);
        g_Vt[b * (NSP * NC) + co * NSP + n] = __float2bfloat16(val);
    }
}

// ============================================================
// 2) M[a][j] = 0.5 * sum_n K[a][n] * J[j][n]
// ============================================================
__global__ __launch_bounds__(256) void m_kernel()
{
    int a = blockIdx.x, j = blockIdx.y, b = blockIdx.z;
    const float* K = g_K + b * (NSP * 8) + a * NSP;
    const float* J = g_J + b * (NSP * 8) + j * NSP;
    float p = 0.f;
    for (int n = threadIdx.x; n < NSP; n += 256) p += K[n] * J[n];
    __shared__ float red[256];
    red[threadIdx.x] = p;
    __syncthreads();
    for (int s = 128; s > 0; s >>= 1) {
        if (threadIdx.x < s) red[threadIdx.x] += red[threadIdx.x + s];
        __syncthreads();
    }
    if (threadIdx.x == 0) g_M[b * 64 + a * 8 + j] = 0.5f * red[0];
}

// ============================================================
// 3) attn: full m-range per block; fused gamma*acc + x epilogue -> out.
// ============================================================
__global__ __launch_bounds__(128) void attn_kernel(
    const float* __restrict__ x, const float* __restrict__ gamma,
    float* __restrict__ out)
{
    const u32 HALF2 = 0x3F003F00u;   // bf16x2 {0.5, 0.5}

    int rt = blockIdx.x, b = blockIdx.y;
    int tid = threadIdx.x, wid = tid >> 5, l = tid & 31;
    int lq = l & 3, lr = l >> 2;
    int rowbase = rt * BLK_ROWS;
    int row0 = rowbase + wid * 16 + lr, row1 = row0 + 8;

    __shared__ float sQ[8][64];
    __shared__ float sM[64];
    __shared__ u32 sKt[2][8][72];              // raw fp32 bits (tf32 by truncation)
    __shared__ __nv_bfloat16 sV[2][32][72];

    const float* Qb = g_Q + b * (NSP * 8);
    const float* Kb = g_K + b * (NSP * 8);
    const __nv_bfloat16* Vtb = g_Vt + b * (NSP * NC);

    if (tid < 64) sM[tid] = g_M[b * 64 + tid];
    {
        int a = tid >> 4, i = (tid & 15) * 4;
        *(float4*)&sQ[a][i] = *(const float4*)(Qb + a * NSP + rowbase + i);
    }

    const int NT = NSP / MT;   // 64 tiles

    int kj = tid >> 4, kmg = (tid & 15) * 4;
    int vc0 = tid >> 3, vmg0 = (tid & 7) * 8;
    int vc1 = (tid + 128) >> 3, vmg1 = vmg0;

    cp16(&sKt[0][kj][kmg], Kb + kj * NSP + kmg);
    cp16(&sV[0][vc0][vmg0], Vtb + vc0 * NSP + vmg0);
    cp16(&sV[0][vc1][vmg1], Vtb + vc1 * NSP + vmg1);
    asm volatile("cp.async.commit_group;");

    __syncthreads();

    float r00 = 0.f, r01 = 0.f, r10 = 0.f, r11 = 0.f;
    int i0 = wid * 16 + lr, i1 = i0 + 8;
    #pragma unroll
    for (int a = 0; a < 8; a++) {
        float q0 = sQ[a][i0], q1 = sQ[a][i1];
        r00 += q0 * sM[a * 8 + lq];
        r01 += q0 * sM[a * 8 + lq + 4];
        r10 += q1 * sM[a * 8 + lq];
        r11 += q1 * sM[a * 8 + lq + 4];
    }
    u32 A32[4] = { tf32c(r00), tf32c(r10), tf32c(r01), tf32c(r11) };

    float acc[16];
    #pragma unroll
    for (int i = 0; i < 16; i++) acc[i] = 0.f;

    for (int ti = 0; ti < NT; ti++) {
        int cur = ti & 1, nxt = cur ^ 1;
        __syncthreads();
        if (ti + 1 < NT) {
            int mb = (ti + 1) * MT;
            cp16(&sKt[nxt][kj][kmg], Kb + kj * NSP + mb + kmg);
            cp16(&sV[nxt][vc0][vmg0], Vtb + vc0 * NSP + mb + vmg0);
            cp16(&sV[nxt][vc1][vmg1], Vtb + vc1 * NSP + mb + vmg1);
        }
        asm volatile("cp.async.commit_group;");
        asm volatile("cp.async.wait_group 1;");
        __syncthreads();

        #pragma unroll
        for (int ch = 0; ch < 4; ch++) {
            int cb = ch * 16;
            u32 kb0a = sKt[cur][lq][cb + lr],     kb1a = sKt[cur][lq + 4][cb + lr];
            u32 kb0b = sKt[cur][lq][cb + 8 + lr], kb1b = sKt[cur][lq + 4][cb + 8 + lr];
            float t[8];
            #pragma unroll
            for (int i = 0; i < 8; i++) t[i] = 0.f;
            mma_tf32(t,     A32, kb0a, kb1a);
            mma_tf32(t + 4, A32, kb0b, kb1b);

            // sigmoid in bf16x2: s = 0.5*tanh(t) + 0.5  (t pre-scaled by 0.5 via M)
            u32 Abf[4];
            Abf[0] = fma_bf2(tanh_bf2(cvt_bf2(t[1], t[0])), HALF2, HALF2);
            Abf[1] = fma_bf2(tanh_bf2(cvt_bf2(t[3], t[2])), HALF2, HALF2);
            Abf[2] = fma_bf2(tanh_bf2(cvt_bf2(t[5], t[4])), HALF2, HALF2);
            Abf[3] = fma_bf2(tanh_bf2(cvt_bf2(t[7], t[6])), HALF2, HALF2);

            int m0 = cb + 2 * lq;
            #pragma unroll
            for (int g = 0; g < 4; g++) {
                int c = g * 8 + lr;
                u32 vb0 = *(const u32*)&sV[cur][c][m0];
                u32 vb1 = *(const u32*)&sV[cur][c][m0 + 8];
                mma16816(acc + g * 4, Abf, vb0, vb1);
            }
        }
    }

    // fused epilogue: out = gamma * acc + x
    float gm = gamma[0];
    const float* Xb = x + b * (NSP * NC);
    float* Ob = out + b * (NSP * NC);
    #pragma unroll
    for (int g = 0; g < 4; g++) {
        int col = g * 8 + lq * 2;
        float2 x0 = *(const float2*)(Xb + row0 * NC + col);
        float2 x1 = *(const float2*)(Xb + row1 * NC + col);
        *(float2*)(Ob + row0 * NC + col) =
            make_float2(gm * acc[g * 4 + 0] + x0.x, gm * acc[g * 4 + 1] + x0.y);
        *(float2*)(Ob + row1 * NC + col) =
            make_float2(gm * acc[g * 4 + 2] + x1.x, gm * acc[g * 4 + 3] + x1.y);
    }
}

// ============================================================
extern "C" void kernel_launch(void* const* d_in, const int* in_sizes, int n_in,
                              void* d_out, int out_size)
{
    const float* x     = (const float*)d_in[0];
    const float* gamma = (const float*)d_in[1];
    const float* qw = (const float*)d_in[2];
    const float* qb = (const float*)d_in[3];
    const float* qs = (const float*)d_in[4];
    const float* qo = (const float*)d_in[5];
    const float* kw = (const float*)d_in[6];
    const float* kb = (const float*)d_in[7];
    const float* ks = (const float*)d_in[8];
    const float* ko = (const float*)d_in[9];
    const float* jw = (const float*)d_in[10];
    const float* jb = (const float*)d_in[11];
    const float* js = (const float*)d_in[12];
    const float* jo = (const float*)d_in[13];
    const float* vw = (const float*)d_in[14];
    const float* vb = (const float*)d_in[15];
    const float* vs = (const float*)d_in[16];
    const float* vo = (const float*)d_in[17];
    float* out = (float*)d_out;

    proj_kernel<<<dim3(16, 16, BATCH), 128>>>(x, qw, qb, qs, qo,
                                              kw, kb, ks, ko,
                                              jw, jb, js, jo,
                                              vw, vb, vs, vo);
    m_kernel<<<dim3(8, 8, BATCH), 256>>>();
    attn_kernel<<<dim3(NSP / BLK_ROWS, BATCH), 128>>>(x, gamma, out);
}

// round 8
// speedup vs baseline: 1.3356x; 1.3356x over previous
#include <cuda_runtime.h>
#include <cuda_bf16.h>

// SpatialAttention, factored: m1@m2 = Qt(K Jt)K -> rank-8 bilinear form.
// R7: proj split-ci (2x warps, half chain); attn MSPLIT=4 with fused
//     counter-based epilogue (finish_kernel removed).

#define BATCH 2
#define NSP   4096
#define NC    32
#define MSPLIT 4
#define MT    64
#define BLK_ROWS 64          // 4 warps x 16 rows

typedef unsigned long long ull;
typedef unsigned int u32;

// ---- scratch ----
__device__ float g_Q[BATCH * NSP * 8];
__device__ float g_K[BATCH * NSP * 8];
__device__ float g_J[BATCH * NSP * 8];
__device__ __nv_bfloat16 g_Vt[BATCH * NC * NSP];   // [b][c][n] bf16
__device__ float g_M[BATCH * 64];                  // 0.5 * (K Jt)
__device__ float g_P[MSPLIT * BATCH * NSP * NC];   // partial sums
__device__ int   g_cnt[(NSP / BLK_ROWS) * BATCH];  // arrival counters (init 0)

#define XIDX(b,w,d,h,c) (((((((b)*16+(w))*16+(d))*16)+(h))*32)+(c))

__device__ __forceinline__ u32 cvt_bf2(float hi, float lo) {
    u32 r; asm("cvt.rn.bf16x2.f32 %0, %1, %2;" : "=r"(r) : "f"(hi), "f"(lo)); return r;
}
__device__ __forceinline__ u32 tanh_bf2(u32 x) {
    u32 r; asm("tanh.approx.bf16x2 %0, %1;" : "=r"(r) : "r"(x)); return r;
}
__device__ __forceinline__ u32 fma_bf2(u32 a, u32 b, u32 c) {
    u32 r; asm("fma.rn.bf16x2 %0, %1, %2, %3;" : "=r"(r) : "r"(a), "r"(b), "r"(c)); return r;
}
__device__ __forceinline__ u32 tf32c(float x) {
    u32 r; asm("cvt.rna.tf32.f32 %0, %1;" : "=r"(r) : "f"(x)); return r;
}
__device__ __forceinline__ void mma_tf32(float* c, const u32* a, u32 b0, u32 b1) {
    asm("mma.sync.aligned.m16n8k8.row.col.f32.tf32.tf32.f32 "
        "{%0,%1,%2,%3}, {%4,%5,%6,%7}, {%8,%9}, {%0,%1,%2,%3};"
        : "+f"(c[0]), "+f"(c[1]), "+f"(c[2]), "+f"(c[3])
        : "r"(a[0]), "r"(a[1]), "r"(a[2]), "r"(a[3]), "r"(b0), "r"(b1));
}
__device__ __forceinline__ void mma16816(float* c, const u32* a, u32 b0, u32 b1) {
    asm("mma.sync.aligned.m16n8k16.row.col.f32.bf16.bf16.f32 "
        "{%0,%1,%2,%3}, {%4,%5,%6,%7}, {%8,%9}, {%0,%1,%2,%3};"
        : "+f"(c[0]), "+f"(c[1]), "+f"(c[2]), "+f"(c[3])
        : "r"(a[0]), "r"(a[1]), "r"(a[2]), "r"(a[3]), "r"(b0), "r"(b1));
}
__device__ __forceinline__ void cp16(void* smem_dst, const void* gsrc) {
    u32 d = (u32)__cvta_generic_to_shared(smem_dst);
    asm volatile("cp.async.ca.shared.global [%0], [%1], 16;" :: "r"(d), "l"(gsrc));
}
__device__ __forceinline__ float2 ldcg2(const float* p) {
    float2 v;
    asm volatile("ld.global.cg.v2.f32 {%0,%1}, [%2];"
                 : "=f"(v.x), "=f"(v.y) : "l"(p));
    return v;
}

// ============================================================
// 1) Projections — ci split across 2 thread groups (256 threads).
// ============================================================
__global__ __launch_bounds__(256) void proj_kernel(
    const float* __restrict__ x,
    const float* __restrict__ qw, const float* __restrict__ qb,
    const float* __restrict__ qs, const float* __restrict__ qo,
    const float* __restrict__ kw, const float* __restrict__ kb,
    const float* __restrict__ ks, const float* __restrict__ ko,
    const float* __restrict__ jw, const float* __restrict__ jb,
    const float* __restrict__ js, const float* __restrict__ jo,
    const float* __restrict__ vw, const float* __restrict__ vb,
    const float* __restrict__ vs, const float* __restrict__ vo)
{
    int d = blockIdx.x, w = blockIdx.y, b = blockIdx.z;
    int tid = threadIdx.x;

    __shared__ float s_c[18][33];
    __shared__ float s_dm[16][33], s_dp[16][33];
    __shared__ float s_wm[16][33], s_wp[16][33];
    __shared__ float s_qw[3][32][8], s_kw[3][32][8], s_jw[3][32][8];
    __shared__ float s_vw[32][32];
    __shared__ float s_part[128][9];   // stride 9: conflict-free combine

    for (int i = tid; i < 768; i += 256) {
        (&s_qw[0][0][0])[i] = qw[i];
        (&s_kw[0][0][0])[i] = kw[i];
        (&s_jw[0][0][0])[i] = jw[i];
    }
    for (int i = tid; i < 1024; i += 256) (&s_vw[0][0])[i] = vw[i];

    for (int i = tid; i < 512; i += 256) {
        int h = i >> 5, c = i & 31;
        s_c [h + 1][c] = x[XIDX(b, w, d, h, c)];
        s_dm[h][c] = (d > 0)  ? x[XIDX(b, w, d - 1, h, c)] : 0.f;
        s_dp[h][c] = (d < 15) ? x[XIDX(b, w, d + 1, h, c)] : 0.f;
        s_wm[h][c] = (w > 0)  ? x[XIDX(b, w - 1, d, h, c)] : 0.f;
        s_wp[h][c] = (w < 15) ? x[XIDX(b, w + 1, d, h, c)] : 0.f;
    }
    if (tid < 32)              s_c[0][tid]       = 0.f;
    else if (tid < 64)         s_c[17][tid - 32] = 0.f;
    __syncthreads();

    int oc = tid & 7, h = (tid >> 3) & 15, sg = tid >> 7;
    int c0 = sg * 16;
    float q = 0.f, k = 0.f, j = 0.f;
    float v0 = 0.f, v1 = 0.f, v2 = 0.f, v3 = 0.f;
    #pragma unroll
    for (int ii = 0; ii < 16; ii++) {
        int ci = c0 + ii;
        float xc  = s_c [h + 1][ci];
        float xdm = s_dm[h][ci], xdp = s_dp[h][ci];
        float xwm = s_wm[h][ci], xwp = s_wp[h][ci];
        float xhm = s_c [h][ci], xhp = s_c [h + 2][ci];
        q += xdm * s_qw[0][ci][oc] + xc * s_qw[1][ci][oc] + xdp * s_qw[2][ci][oc];
        k += xwm * s_kw[0][ci][oc] + xc * s_kw[1][ci][oc] + xwp * s_kw[2][ci][oc];
        j += xhm * s_jw[0][ci][oc] + xc * s_jw[1][ci][oc] + xhp * s_jw[2][ci][oc];
        v0 += xc * s_vw[ci][oc];
        v1 += xc * s_vw[ci][oc + 8];
        v2 += xc * s_vw[ci][oc + 16];
        v3 += xc * s_vw[ci][oc + 24];
    }

    if (sg) {
        float* p = s_part[tid & 127];
        p[0] = q;  p[1] = k;  p[2] = j;
        p[3] = v0; p[4] = v1; p[5] = v2; p[6] = v3;
    }
    __syncthreads();
    if (!sg) {
        const float* p = s_part[tid];
        q += p[0]; k += p[1]; j += p[2];
        v0 += p[3]; v1 += p[4]; v2 += p[5]; v3 += p[6];

        int n = w * 256 + d * 16 + h;
        g_Q[b * (NSP * 8) + n * 8 + oc] = fmaxf((q + qb[oc]) * qs[oc] + qo[oc], 0.f);
        g_K[b * (NSP * 8) + n * 8 + oc] = fmaxf((k + kb[oc]) * ks[oc] + ko[oc], 0.f);
        g_J[b * (NSP * 8) + n * 8 + oc] = fmaxf((j + jb[oc]) * js[oc] + jo[oc], 0.f);
        float vv[4] = {v0, v1, v2, v3};
        #pragma unroll
        for (int p4 = 0; p4 < 4; p4++) {
            int co = oc + 8 * p4;
            float val = fmaxf((vv[p4] + vb[co]) * vs[co] + vo[co], 0.f);
            g_Vt[b * (NSP * NC) + co * NSP + n] = __float2bfloat16(val);
        }
    }
}

// ============================================================
// 2) M[a][j] = 0.5 * sum_n K[a][n] * J[j][n]
// ============================================================
__global__ __launch_bounds__(256) void m_kernel()
{
    int a = blockIdx.x, j = blockIdx.y, b = blockIdx.z;
    const float* K = g_K + b * (NSP * 8) + a * NSP;
    const float* J = g_J + b * (NSP * 8) + j * NSP;
    float p = 0.f;
    for (int n = threadIdx.x; n < NSP; n += 256) p += K[n] * J[n];
    __shared__ float red[256];
    red[threadIdx.x] = p;
    __syncthreads();
    for (int s = 128; s > 0; s >>= 1) {
        if (threadIdx.x < s) red[threadIdx.x] += red[threadIdx.x + s];
        __syncthreads();
    }
    if (threadIdx.x == 0) g_M[b * 64 + a * 8 + j] = 0.5f * red[0];
}

// ============================================================
// 3) attn (MSPLIT=4) + fused counter-based reduce epilogue.
// ============================================================
__global__ __launch_bounds__(128) void attn_kernel(
    const float* __restrict__ x, const float* __restrict__ gamma,
    float* __restrict__ out)
{
    const u32 HALF2 = 0x3F003F00u;   // bf16x2 {0.5, 0.5}

    int ms = blockIdx.x, rt = blockIdx.y, b = blockIdx.z;
    int tid = threadIdx.x, wid = tid >> 5, l = tid & 31;
    int lq = l & 3, lr = l >> 2;
    int rowbase = rt * BLK_ROWS;
    int row0 = rowbase + wid * 16 + lr, row1 = row0 + 8;

    __shared__ float sQ[8][64];
    __shared__ float sM[64];
    __shared__ u32 sKt[2][8][72];              // raw fp32 bits (tf32 by truncation)
    __shared__ __nv_bfloat16 sV[2][32][72];

    const float* Qb = g_Q + b * (NSP * 8);
    const float* Kb = g_K + b * (NSP * 8);
    const __nv_bfloat16* Vtb = g_Vt + b * (NSP * NC);

    if (tid < 64) sM[tid] = g_M[b * 64 + tid];
    {
        int a = tid >> 4, i = (tid & 15) * 4;
        *(float4*)&sQ[a][i] = *(const float4*)(Qb + a * NSP + rowbase + i);
    }

    const int mbeg = ms * (NSP / MSPLIT);
    const int NT = (NSP / MSPLIT) / MT;

    int kj = tid >> 4, kmg = (tid & 15) * 4;
    int vc0 = tid >> 3, vmg0 = (tid & 7) * 8;
    int vc1 = (tid + 128) >> 3, vmg1 = vmg0;

    cp16(&sKt[0][kj][kmg], Kb + kj * NSP + mbeg + kmg);
    cp16(&sV[0][vc0][vmg0], Vtb + vc0 * NSP + mbeg + vmg0);
    cp16(&sV[0][vc1][vmg1], Vtb + vc1 * NSP + mbeg + vmg1);
    asm volatile("cp.async.commit_group;");

    __syncthreads();

    float r00 = 0.f, r01 = 0.f, r10 = 0.f, r11 = 0.f;
    int i0 = wid * 16 + lr, i1 = i0 + 8;
    #pragma unroll
    for (int a = 0; a < 8; a++) {
        float q0 = sQ[a][i0], q1 = sQ[a][i1];
        r00 += q0 * sM[a * 8 + lq];
        r01 += q0 * sM[a * 8 + lq + 4];
        r10 += q1 * sM[a * 8 + lq];
        r11 += q1 * sM[a * 8 + lq + 4];
    }
    u32 A32[4] = { tf32c(r00), tf32c(r10), tf32c(r01), tf32c(r11) };

    float acc[16];
    #pragma unroll
    for (int i = 0; i < 16; i++) acc[i] = 0.f;

    for (int ti = 0; ti < NT; ti++) {
        int cur = ti & 1, nxt = cur ^ 1;
        __syncthreads();
        if (ti + 1 < NT) {
            int mb = mbeg + (ti + 1) * MT;
            cp16(&sKt[nxt][kj][kmg], Kb + kj * NSP + mb + kmg);
            cp16(&sV[nxt][vc0][vmg0], Vtb + vc0 * NSP + mb + vmg0);
            cp16(&sV[nxt][vc1][vmg1], Vtb + vc1 * NSP + mb + vmg1);
        }
        asm volatile("cp.async.commit_group;");
        asm volatile("cp.async.wait_group 1;");
        __syncthreads();

        #pragma unroll
        for (int ch = 0; ch < 4; ch++) {
            int cb = ch * 16;
            u32 kb0a = sKt[cur][lq][cb + lr],     kb1a = sKt[cur][lq + 4][cb + lr];
            u32 kb0b = sKt[cur][lq][cb + 8 + lr], kb1b = sKt[cur][lq + 4][cb + 8 + lr];
            float t[8];
            #pragma unroll
            for (int i = 0; i < 8; i++) t[i] = 0.f;
            mma_tf32(t,     A32, kb0a, kb1a);
            mma_tf32(t + 4, A32, kb0b, kb1b);

            u32 Abf[4];
            Abf[0] = fma_bf2(tanh_bf2(cvt_bf2(t[1], t[0])), HALF2, HALF2);
            Abf[1] = fma_bf2(tanh_bf2(cvt_bf2(t[3], t[2])), HALF2, HALF2);
            Abf[2] = fma_bf2(tanh_bf2(cvt_bf2(t[5], t[4])), HALF2, HALF2);
            Abf[3] = fma_bf2(tanh_bf2(cvt_bf2(t[7], t[6])), HALF2, HALF2);

            int m0 = cb + 2 * lq;
            #pragma unroll
            for (int g = 0; g < 4; g++) {
                int c = g * 8 + lr;
                u32 vb0 = *(const u32*)&sV[cur][c][m0];
                u32 vb1 = *(const u32*)&sV[cur][c][m0 + 8];
                mma16816(acc + g * 4, Abf, vb0, vb1);
            }
        }
    }

    // write partials
    float* P = g_P + ((size_t)(ms * BATCH + b) * NSP) * NC;
    #pragma unroll
    for (int g = 0; g < 4; g++) {
        int col = g * 8 + lq * 2;
        *(float2*)(P + row0 * NC + col) = make_float2(acc[g * 4 + 0], acc[g * 4 + 1]);
        *(float2*)(P + row1 * NC + col) = make_float2(acc[g * 4 + 2], acc[g * 4 + 3]);
    }

    // fused reduce: last-arriving block of the (rt,b) group sums 4 partials.
    __threadfence();
    __shared__ int s_old;
    if (tid == 0) s_old = atomicAdd(&g_cnt[rt * BATCH + b], 1);
    __syncthreads();
    if (s_old == MSPLIT - 1) {
        if (tid == 0) g_cnt[rt * BATCH + b] = 0;   // reset for next replay
        __threadfence_block();
        float gm = gamma[0];
        size_t tile = (size_t)rowbase * NC;        // 2048 floats per group
        const float* Xb = x + (size_t)b * NSP * NC + tile;
        float* Ob = out + (size_t)b * NSP * NC + tile;
        #pragma unroll
        for (int kk = 0; kk < 8; kk++) {
            int off = kk * 256 + tid * 2;
            float2 s = ldcg2(g_P + ((size_t)b * NSP) * NC + tile + off);
            #pragma unroll
            for (int sp = 1; sp < MSPLIT; sp++) {
                float2 p = ldcg2(g_P + ((size_t)(sp * BATCH + b) * NSP) * NC + tile + off);
                s.x += p.x; s.y += p.y;
            }
            float2 xv = *(const float2*)(Xb + off);
            *(float2*)(Ob + off) = make_float2(gm * s.x + xv.x, gm * s.y + xv.y);
        }
    }
}

// ============================================================
extern "C" void kernel_launch(void* const* d_in, const int* in_sizes, int n_in,
                              void* d_out, int out_size)
{
    const float* x     = (const float*)d_in[0];
    const float* gamma = (const float*)d_in[1];
    const float* qw = (const float*)d_in[2];
    const float* qb = (const float*)d_in[3];
    const float* qs = (const float*)d_in[4];
    const float* qo = (const float*)d_in[5];
    const float* kw = (const float*)d_in[6];
    const float* kb = (const float*)d_in[7];
    const float* ks = (const float*)d_in[8];
    const float* ko = (const float*)d_in[9];
    const float* jw = (const float*)d_in[10];
    const float* jb = (const float*)d_in[11];
    const float* js = (const float*)d_in[12];
    const float* jo = (const float*)d_in[13];
    const float* vw = (const float*)d_in[14];
    const float* vb = (const float*)d_in[15];
    const float* vs = (const float*)d_in[16];
    const float* vo = (const float*)d_in[17];
    float* out = (float*)d_out;

    proj_kernel<<<dim3(16, 16, BATCH), 256>>>(x, qw, qb, qs, qo,
                                              kw, kb, ks, ko,
                                              jw, jb, js, jo,
                                              vw, vb, vs, vo);
    m_kernel<<<dim3(8, 8, BATCH), 256>>>();
    attn_kernel<<<dim3(MSPLIT, NSP / BLK_ROWS, BATCH), 128>>>(x, gamma, out);
}